// round 1
// baseline (speedup 1.0000x reference)
#include <cuda_runtime.h>
#include <cuda_bf16.h>
#include <math.h>

// Problem constants
#define B_   16
#define C_   128
#define IHW  32
#define N_   1024      // 32*32
#define H_   4
#define D_   32
#define CN   (C_*N_)   // 131072 elements per (proj, batch)

// ---------------- scratch (device globals; no allocations) ----------------
__device__ float g_conv[3][B_*CN];        // conv outputs, [p][b][c][n]
__device__ float g_qkv [3][B_*CN];        // head-major [p][(b*4+h)][n][d]
__device__ float g_mean[48];
__device__ float g_rstd[48];
__device__ float g_bias4[H_*N_*N_];       // [h][n][m]  (16 MB, L2 resident)
__device__ float g_attn[B_*N_*C_];        // [b][n][c]  attention output (n-major)

// =====================================================================
// Kernel 1: conv3x3 (stride1 pad1, no bias).  Tile: 16 cout x (8 rows x 32 cols)
// block 256 threads, each thread owns 8 cout x 2 spatial positions.
// =====================================================================
__global__ __launch_bounds__(256) void conv3x3_kernel(
    const float* __restrict__ x, const float* __restrict__ w, int p)
{
    __shared__ float in_t[16][10][34];   // ci chunk x (8+2 rows) x (32+2 cols)
    __shared__ float w_t[16][16][9];     // [co_local][ci_local][k]

    const int b    = blockIdx.z;
    const int row0 = blockIdx.y * 8;
    const int co0  = blockIdx.x * 16;
    const int tid  = threadIdx.x;
    const int ts   = tid & 127;
    const int col  = ts & 31;
    const int row  = ts >> 5;      // 0..3 (second position = row+4)
    const int cg   = tid >> 7;     // 0..1 -> cout sub-group of 8

    float acc0[8], acc1[8];
#pragma unroll
    for (int j = 0; j < 8; j++) { acc0[j] = 0.f; acc1[j] = 0.f; }

    const float* xb = x + b * CN;

    for (int ci0 = 0; ci0 < 128; ci0 += 16) {
        __syncthreads();
        // load input tile (with halo, zero padded)
        for (int e = tid; e < 16*10*34; e += 256) {
            int ci  = e / 340;
            int rem = e - ci * 340;
            int rr  = rem / 34;
            int cc  = rem - rr * 34;
            int gr  = row0 - 1 + rr;
            int gc  = cc - 1;
            float v = 0.f;
            if ((unsigned)gr < 32u && (unsigned)gc < 32u)
                v = xb[(ci0 + ci) * N_ + gr * 32 + gc];
            in_t[ci][rr][cc] = v;
        }
        // load weight tile
        for (int e = tid; e < 16*16*9; e += 256) {
            int co  = e / 144;
            int rem = e - co * 144;
            int ci  = rem / 9;
            int k   = rem - ci * 9;
            w_t[co][ci][k] = w[((co0 + co) * 128 + ci0 + ci) * 9 + k];
        }
        __syncthreads();

        for (int ci = 0; ci < 16; ci++) {
#pragma unroll
            for (int dy = 0; dy < 3; dy++) {
#pragma unroll
                for (int dx = 0; dx < 3; dx++) {
                    float iv0 = in_t[ci][row + dy][col + dx];
                    float iv1 = in_t[ci][row + 4 + dy][col + dx];
#pragma unroll
                    for (int j = 0; j < 8; j++) {
                        float wv = w_t[cg * 8 + j][ci][dy * 3 + dx];
                        acc0[j] += iv0 * wv;
                        acc1[j] += iv1 * wv;
                    }
                }
            }
        }
    }

    float* out = g_conv[p] + b * CN;
#pragma unroll
    for (int j = 0; j < 8; j++) {
        int co = co0 + cg * 8 + j;
        out[co * N_ + (row0 + row)     * 32 + col] = acc0[j];
        out[co * N_ + (row0 + row + 4) * 32 + col] = acc1[j];
    }
}

// =====================================================================
// Kernel 2: deterministic mean/var per (proj, batch).  48 blocks.
// =====================================================================
__global__ __launch_bounds__(256) void gn_reduce_kernel()
{
    const int blk = blockIdx.x;          // p*16 + b
    const int p = blk >> 4, b = blk & 15;
    const float* src = g_conv[p] + b * CN;
    const int tid = threadIdx.x;

    double s = 0.0, s2 = 0.0;
    for (int i = tid; i < CN; i += 256) {
        float v = src[i];
        s  += (double)v;
        s2 += (double)v * (double)v;
    }
    __shared__ double a[256], a2[256];
    a[tid] = s; a2[tid] = s2;
    __syncthreads();
    for (int st = 128; st > 0; st >>= 1) {
        if (tid < st) { a[tid] += a[tid + st]; a2[tid] += a2[tid + st]; }
        __syncthreads();
    }
    if (tid == 0) {
        double mean = a[0] / (double)CN;
        double var  = a2[0] / (double)CN - mean * mean;
        g_mean[blk] = (float)mean;
        g_rstd[blk] = (float)(1.0 / sqrt(var + 1e-6));
    }
}

// =====================================================================
// Kernel 3: GroupNorm apply + exact GELU + transpose to head-major layout
// grid: (16 n-tiles of 64, 4 heads, 48 pb)
// =====================================================================
__global__ __launch_bounds__(256) void norm_gelu_kernel(
    const float* __restrict__ gq, const float* __restrict__ bq,
    const float* __restrict__ gk, const float* __restrict__ bk,
    const float* __restrict__ gv, const float* __restrict__ bv)
{
    const int pb = blockIdx.z;
    const int p = pb >> 4, b = pb & 15;
    const int h = blockIdx.y;
    const int n0 = blockIdx.x * 64;
    const int tid = threadIdx.x;

    const float* gamma = (p == 0) ? gq : (p == 1) ? gk : gv;
    const float* beta  = (p == 0) ? bq : (p == 1) ? bk : bv;
    const float mean = g_mean[pb];
    const float rstd = g_rstd[pb];

    __shared__ float s[32][65];

    const float* src = g_conv[p] + (b * 128 + h * 32) * N_;
    for (int e = tid; e < 2048; e += 256) {
        int d = e >> 6, nn = e & 63;
        float v = src[d * N_ + n0 + nn];
        int c = h * 32 + d;
        v = (v - mean) * rstd * gamma[c] + beta[c];
        v = 0.5f * v * (1.0f + erff(v * 0.70710678118654752f));
        s[d][nn] = v;
    }
    __syncthreads();
    float* dst = g_qkv[p] + ((b * 4 + h) * N_ + n0) * D_;
    for (int e = tid; e < 2048; e += 256) {
        int nn = e >> 5, d = e & 31;
        dst[nn * D_ + d] = s[d][nn];
    }
}

// =====================================================================
// Kernel 4: materialize bias[h][n][m] from table gather
// =====================================================================
__global__ __launch_bounds__(256) void bias_kernel(
    const float* __restrict__ table, const int* __restrict__ rel_index)
{
    const int n = blockIdx.x;
    for (int m = threadIdx.x; m < N_; m += 256) {
        int idx = rel_index[n * N_ + m];
        float4 t = *reinterpret_cast<const float4*>(table + idx * 4);
        g_bias4[(0 * N_ + n) * N_ + m] = t.x;
        g_bias4[(1 * N_ + n) * N_ + m] = t.y;
        g_bias4[(2 * N_ + n) * N_ + m] = t.z;
        g_bias4[(3 * N_ + n) * N_ + m] = t.w;
    }
}

// =====================================================================
// Kernel 5: attention (flash-style, online softmax).
// grid: (16 q-tiles of 64 rows, 64 bh).  block 256 = 8 warps, warp owns 8 rows.
// lane l owns output column d=l.  K/V chunks of 64.
// =====================================================================
__global__ __launch_bounds__(256) void attn_kernel()
{
    __shared__ float Qs[64 * 32];       // [r][d], float4-aligned rows
    __shared__ float Ks[64 * 33];       // [m][d] padded
    __shared__ float Vs[64 * 33];       // [m][d] padded
    __shared__ float Ps[64 * 64];       // [r][m] scores / probs

    const int tid  = threadIdx.x;
    const int lane = tid & 31;
    const int wrp  = tid >> 5;          // 0..7
    const int qt   = blockIdx.x;
    const int bh   = blockIdx.y;
    const int b    = bh >> 2;
    const int h    = bh & 3;

    const float* qbase = g_qkv[0] + (size_t)bh * N_ * D_;
    const float* kbase = g_qkv[1] + (size_t)bh * N_ * D_;
    const float* vbase = g_qkv[2] + (size_t)bh * N_ * D_;

    // load Q tile (64 x 32)
    for (int e = tid; e < 2048; e += 256)
        Qs[e] = qbase[qt * 64 * D_ + e];

    float m_run[8], l_run[8], acc[8];
#pragma unroll
    for (int rr = 0; rr < 8; rr++) {
        m_run[rr] = -INFINITY; l_run[rr] = 0.f; acc[rr] = 0.f;
    }

    for (int kc = 0; kc < 16; kc++) {
        const int m0 = kc * 64;
        __syncthreads();
        for (int e = tid; e < 2048; e += 256) {
            int mm = e >> 5, d = e & 31;
            Ks[mm * 33 + d] = kbase[(m0 + mm) * D_ + d];
            Vs[mm * 33 + d] = vbase[(m0 + mm) * D_ + d];
        }
        __syncthreads();

        // ---- scores: S = Q K^T + bias, staged to Ps ----
#pragma unroll
        for (int pass = 0; pass < 2; pass++) {
            const int mloc = pass * 32 + lane;
            float kreg[32];
#pragma unroll
            for (int kk = 0; kk < 32; kk++) kreg[kk] = Ks[mloc * 33 + kk];
#pragma unroll
            for (int rr = 0; rr < 8; rr++) {
                const int r = wrp * 8 + rr;
                const float4* qp = reinterpret_cast<const float4*>(Qs + r * 32);
                float s = 0.f;
#pragma unroll
                for (int q4 = 0; q4 < 8; q4++) {
                    float4 qv = qp[q4];
                    s += qv.x * kreg[q4 * 4 + 0];
                    s += qv.y * kreg[q4 * 4 + 1];
                    s += qv.z * kreg[q4 * 4 + 2];
                    s += qv.w * kreg[q4 * 4 + 3];
                }
                s += g_bias4[((size_t)h * N_ + qt * 64 + r) * N_ + m0 + mloc];
                Ps[r * 64 + mloc] = s;
            }
        }
        __syncwarp();

        // ---- online softmax update (per warp-owned rows) ----
#pragma unroll
        for (int rr = 0; rr < 8; rr++) {
            const int r = wrp * 8 + rr;
            float s0 = Ps[r * 64 + lane];
            float s1 = Ps[r * 64 + lane + 32];
            float cm = fmaxf(s0, s1);
#pragma unroll
            for (int off = 16; off > 0; off >>= 1)
                cm = fmaxf(cm, __shfl_xor_sync(0xffffffffu, cm, off));
            float mnew = fmaxf(m_run[rr], cm);
            float corr = expf(m_run[rr] - mnew);
            float p0 = expf(s0 - mnew);
            float p1 = expf(s1 - mnew);
            Ps[r * 64 + lane]      = p0;
            Ps[r * 64 + lane + 32] = p1;
            float ls = p0 + p1;
#pragma unroll
            for (int off = 16; off > 0; off >>= 1)
                ls += __shfl_xor_sync(0xffffffffu, ls, off);
            l_run[rr] = l_run[rr] * corr + ls;
            m_run[rr] = mnew;
            acc[rr]  *= corr;
        }
        __syncwarp();

        // ---- O += P V  (lane owns column d = lane) ----
#pragma unroll
        for (int sub = 0; sub < 2; sub++) {
            float vreg[32];
#pragma unroll
            for (int i = 0; i < 32; i++)
                vreg[i] = Vs[(sub * 32 + i) * 33 + lane];
#pragma unroll
            for (int rr = 0; rr < 8; rr++) {
                const int r = wrp * 8 + rr;
                const float4* pp = reinterpret_cast<const float4*>(Ps + r * 64 + sub * 32);
                float a = acc[rr];
#pragma unroll
                for (int i4 = 0; i4 < 8; i4++) {
                    float4 pv = pp[i4];
                    a += pv.x * vreg[i4 * 4 + 0];
                    a += pv.y * vreg[i4 * 4 + 1];
                    a += pv.z * vreg[i4 * 4 + 2];
                    a += pv.w * vreg[i4 * 4 + 3];
                }
                acc[rr] = a;
            }
        }
    }

    // write output, n-major layout [b][n][c]
#pragma unroll
    for (int rr = 0; rr < 8; rr++) {
        const int n = qt * 64 + wrp * 8 + rr;
        g_attn[((size_t)b * N_ + n) * C_ + h * 32 + lane] = acc[rr] / l_run[rr];
    }
}

// =====================================================================
// Kernel 6: 1x1 conv (GEMM) + bias.  grid (8 n-tiles of 128, 16 b).
// thread owns 32 cout x 2 n positions.
// =====================================================================
__global__ __launch_bounds__(256) void outconv_kernel(
    const float* __restrict__ w, const float* __restrict__ bias,
    float* __restrict__ out)
{
    __shared__ float a_t[128][33];
    __shared__ float w_t[128][32];

    const int b  = blockIdx.y;
    const int n0 = blockIdx.x * 128;
    const int tid = threadIdx.x;
    const int nl  = tid & 63;
    const int cog = tid >> 6;   // 0..3 -> cout group of 32

    float acc0[32], acc1[32];
#pragma unroll
    for (int j = 0; j < 32; j++) { acc0[j] = 0.f; acc1[j] = 0.f; }

    for (int c0 = 0; c0 < 128; c0 += 32) {
        __syncthreads();
        for (int e = tid; e < 4096; e += 256) {
            int nn = e >> 5, cc = e & 31;
            a_t[nn][cc] = g_attn[((size_t)b * N_ + n0 + nn) * C_ + c0 + cc];
        }
        for (int e = tid; e < 4096; e += 256) {
            int co = e >> 5, cc = e & 31;
            w_t[co][cc] = w[co * 128 + c0 + cc];
        }
        __syncthreads();
#pragma unroll
        for (int cc = 0; cc < 32; cc++) {
            float a0 = a_t[nl][cc];
            float a1 = a_t[nl + 64][cc];
#pragma unroll
            for (int j = 0; j < 32; j++) {
                float wv = w_t[cog * 32 + j][cc];
                acc0[j] += a0 * wv;
                acc1[j] += a1 * wv;
            }
        }
    }
#pragma unroll
    for (int j = 0; j < 32; j++) {
        int co = cog * 32 + j;
        float bv = bias[co];
        out[((size_t)b * 128 + co) * N_ + n0 + nl]      = acc0[j] + bv;
        out[((size_t)b * 128 + co) * N_ + n0 + nl + 64] = acc1[j] + bv;
    }
}

// =====================================================================
extern "C" void kernel_launch(void* const* d_in, const int* in_sizes, int n_in,
                              void* d_out, int out_size)
{
    const float* x      = (const float*)d_in[0];
    const float* wq     = (const float*)d_in[1];
    const float* gq     = (const float*)d_in[2];
    const float* bq     = (const float*)d_in[3];
    const float* wk     = (const float*)d_in[4];
    const float* gk     = (const float*)d_in[5];
    const float* bk     = (const float*)d_in[6];
    const float* wv     = (const float*)d_in[7];
    const float* gv     = (const float*)d_in[8];
    const float* bv     = (const float*)d_in[9];
    const float* table  = (const float*)d_in[10];
    const int*   relidx = (const int*)  d_in[11];
    const float* out_w  = (const float*)d_in[12];
    const float* out_b  = (const float*)d_in[13];
    float* out = (float*)d_out;

    dim3 cgrid(8, 4, 16);
    conv3x3_kernel<<<cgrid, 256>>>(x, wq, 0);
    conv3x3_kernel<<<cgrid, 256>>>(x, wk, 1);
    conv3x3_kernel<<<cgrid, 256>>>(x, wv, 2);

    gn_reduce_kernel<<<48, 256>>>();

    norm_gelu_kernel<<<dim3(16, 4, 48), 256>>>(gq, bq, gk, bk, gv, bv);

    bias_kernel<<<1024, 256>>>(table, relidx);

    attn_kernel<<<dim3(16, 64), 256>>>();

    outconv_kernel<<<dim3(8, 16), 256>>>(out_w, out_b, out);
}